// round 9
// baseline (speedup 1.0000x reference)
#include <cuda_runtime.h>
#include <cuda_bf16.h>
#include <stdint.h>
#include <math.h>

#define TOK 8192
#define HID 1024
#define RNK 256
#define FFN 4096
#define NE  8
#define ERK (NE*RNK)  // 2048
#define NPAIR 28
#define MAXT1 136
#define MAXT2 92

#define NTHREADS 256
#define ROWB 80
#define A_T (128*ROWB)            // 10240
#define B_T (256*ROWB)            // 20480
#define STG (2*A_T + 2*B_T)       // 61440
#define SMEM_BYTES (2*STG)        // 122880

// ---------------------------------------------------------------------------
// Scratch (device globals)
// ---------------------------------------------------------------------------
__device__ float g_mw[TOK * NE];
__device__ int g_e0t[TOK], g_e1t[TOK], g_pidt[TOK];
__device__ int g_pcnt[NPAIR], g_poff[NPAIR], g_pfill[NPAIR], g_ptok[TOK];
__device__ int g_ecnt[NE], g_eoff[NE], g_efill[NE], g_etok[2 * TOK];
__device__ int g_t1grp[MAXT1], g_t1row[MAXT1];
__device__ int g_t2grp[MAXT2], g_t2row[MAXT2];
__device__ int g_pe0[NPAIR], g_pe1[NPAIR];
__device__ int g_meta[2];

__device__ __nv_bfloat16 g_xh[(size_t)TOK * HID], g_xl[(size_t)TOK * HID];
__device__ __nv_bfloat16 g_th[(size_t)TOK * ERK], g_tl[(size_t)TOK * ERK];
__device__ __nv_bfloat16 g_hh[(size_t)TOK * FFN], g_hl[(size_t)TOK * FFN];
__device__ __nv_bfloat16 g_w1h[(size_t)ERK * HID], g_w1l[(size_t)ERK * HID];
__device__ __nv_bfloat16 g_w2h[(size_t)FFN * ERK], g_w2l[(size_t)FFN * ERK];
__device__ __nv_bfloat16 g_w3h[(size_t)HID * FFN], g_w3l[(size_t)HID * FFN];

// ---------------------------------------------------------------------------
// PTX helpers (base sm_103 target)
// ---------------------------------------------------------------------------
__device__ __forceinline__ uint32_t s2u(const void* p) {
    uint32_t a;
    asm("{ .reg .u64 t; cvta.to.shared.u64 t, %1; cvt.u32.u64 %0, t; }" : "=r"(a) : "l"(p));
    return a;
}
__device__ __forceinline__ void cp16(uint32_t dst, const void* src) {
    asm volatile("cp.async.cg.shared.global [%0], [%1], 16;" :: "r"(dst), "l"(src) : "memory");
}
__device__ __forceinline__ void cp_commit() {
    asm volatile("cp.async.commit_group;" ::: "memory");
}
template <int N>
__device__ __forceinline__ void cp_wait() {
    asm volatile("cp.async.wait_group %0;" :: "n"(N) : "memory");
}
__device__ __forceinline__ void ldsm4(uint32_t* r, uint32_t addr) {
    asm volatile("ldmatrix.sync.aligned.m8n8.x4.shared.b16 {%0,%1,%2,%3}, [%4];"
                 : "=r"(r[0]), "=r"(r[1]), "=r"(r[2]), "=r"(r[3]) : "r"(addr));
}
__device__ __forceinline__ void mma16816(float* c, const uint32_t* a, const uint32_t* b) {
    asm volatile(
        "mma.sync.aligned.m16n8k16.row.col.f32.bf16.bf16.f32 "
        "{%0,%1,%2,%3}, {%4,%5,%6,%7}, {%8,%9}, {%0,%1,%2,%3};"
        : "+f"(c[0]), "+f"(c[1]), "+f"(c[2]), "+f"(c[3])
        : "r"(a[0]), "r"(a[1]), "r"(a[2]), "r"(a[3]), "r"(b[0]), "r"(b[1]));
}
__device__ __forceinline__ void split_bf16(float v, __nv_bfloat16& hi, __nv_bfloat16& lo) {
    hi = __float2bfloat16(v);
    lo = __float2bfloat16(v - __bfloat162float(hi));
}

// ---------------------------------------------------------------------------
// Routing infrastructure
// ---------------------------------------------------------------------------
__global__ void zero_kernel() {
    int i = threadIdx.x;
    if (i < NPAIR) { g_pcnt[i] = 0; g_pfill[i] = 0; }
    if (i < NE)    { g_ecnt[i] = 0; g_efill[i] = 0; }
}

__global__ void router_kernel(const float* __restrict__ x,
                              const float* __restrict__ rw,
                              const float* __restrict__ rb) {
    int warp = (blockIdx.x * blockDim.x + threadIdx.x) >> 5;
    int lane = threadIdx.x & 31;
    if (warp >= TOK) return;

    const float4* xr = reinterpret_cast<const float4*>(x + (size_t)warp * HID);
    float acc[NE];
#pragma unroll
    for (int e = 0; e < NE; e++) acc[e] = 0.f;

    for (int i = lane; i < HID / 4; i += 32) {
        float4 xv = xr[i];
        int h = i * 4;
        const float4* w0 = reinterpret_cast<const float4*>(rw + (size_t)h * NE);
        float4 a0 = w0[0], a1 = w0[1];
        float4 b0 = w0[2], b1 = w0[3];
        float4 c0 = w0[4], c1 = w0[5];
        float4 d0 = w0[6], d1 = w0[7];
        acc[0] += xv.x*a0.x + xv.y*b0.x + xv.z*c0.x + xv.w*d0.x;
        acc[1] += xv.x*a0.y + xv.y*b0.y + xv.z*c0.y + xv.w*d0.y;
        acc[2] += xv.x*a0.z + xv.y*b0.z + xv.z*c0.z + xv.w*d0.z;
        acc[3] += xv.x*a0.w + xv.y*b0.w + xv.z*c0.w + xv.w*d0.w;
        acc[4] += xv.x*a1.x + xv.y*b1.x + xv.z*c1.x + xv.w*d1.x;
        acc[5] += xv.x*a1.y + xv.y*b1.y + xv.z*c1.y + xv.w*d1.y;
        acc[6] += xv.x*a1.z + xv.y*b1.z + xv.z*c1.z + xv.w*d1.z;
        acc[7] += xv.x*a1.w + xv.y*b1.w + xv.z*c1.w + xv.w*d1.w;
    }
#pragma unroll
    for (int e = 0; e < NE; e++) {
#pragma unroll
        for (int o = 16; o > 0; o >>= 1)
            acc[e] += __shfl_xor_sync(0xffffffffu, acc[e], o);
    }
    if (lane == 0) {
        float lg[NE], m = -1e30f;
#pragma unroll
        for (int e = 0; e < NE; e++) { lg[e] = acc[e] + rb[e]; m = fmaxf(m, lg[e]); }
        float p[NE], s = 0.f;
#pragma unroll
        for (int e = 0; e < NE; e++) { p[e] = expf(lg[e] - m); s += p[e]; }
        float inv = 1.f / s;
        int i0 = 0;
#pragma unroll
        for (int e = 1; e < NE; e++) if (p[e] > p[i0]) i0 = e;
        int i1 = (i0 == 0) ? 1 : 0;
#pragma unroll
        for (int e = 0; e < NE; e++) { if (e == i0) continue; if (p[e] > p[i1]) i1 = e; }
#pragma unroll
        for (int e = 0; e < NE; e++)
            g_mw[warp * NE + e] = (e == i0 || e == i1) ? p[e] * inv : 0.f;
        int e0 = min(i0, i1), e1 = max(i0, i1);
        int pid = e0 * (2 * NE - e0 - 1) / 2 + (e1 - e0 - 1);
        g_e0t[warp] = e0; g_e1t[warp] = e1; g_pidt[warp] = pid;
        atomicAdd(&g_pcnt[pid], 1);
        atomicAdd(&g_ecnt[e0], 1);
        atomicAdd(&g_ecnt[e1], 1);
    }
}

__global__ void plan_kernel() {
    __shared__ int sec[NE], spc[NPAIR];
    int lane = threadIdx.x;
    if (lane < NE) sec[lane] = g_ecnt[lane];
    if (lane < NPAIR) spc[lane] = g_pcnt[lane];
    __syncwarp();
    if (lane != 0) return;
    int off = 0, nt = 0;
    for (int e = 0; e < NE; e++) {
        g_eoff[e] = off;
        for (int r = 0; r < sec[e]; r += 128) { g_t1grp[nt] = e; g_t1row[nt] = r; nt++; }
        off += sec[e];
    }
    g_meta[0] = nt;
    off = 0; nt = 0;
    int p = 0;
    for (int a = 0; a < NE; a++)
        for (int b = a + 1; b < NE; b++) {
            g_pe0[p] = a; g_pe1[p] = b;
            g_poff[p] = off;
            for (int r = 0; r < spc[p]; r += 128) { g_t2grp[nt] = p; g_t2row[nt] = r; nt++; }
            off += spc[p];
            p++;
        }
    g_meta[1] = nt;
}

__global__ void scatter_kernel() {
    int t = blockIdx.x * blockDim.x + threadIdx.x;
    if (t >= TOK) return;
    int pid = g_pidt[t];
    int pos = atomicAdd(&g_pfill[pid], 1);
    g_ptok[g_poff[pid] + pos] = t;
    int e0 = g_e0t[t], e1 = g_e1t[t];
    pos = atomicAdd(&g_efill[e0], 1); g_etok[g_eoff[e0] + pos] = t;
    pos = atomicAdd(&g_efill[e1], 1); g_etok[g_eoff[e1] + pos] = t;
}

// ---------------------------------------------------------------------------
// Conversions
// ---------------------------------------------------------------------------
__global__ void convert_x_kernel(const float* __restrict__ x,
                                 __nv_bfloat16* __restrict__ xh,
                                 __nv_bfloat16* __restrict__ xl) {
    size_t i = (size_t)blockIdx.x * blockDim.x + threadIdx.x;
    float4 v = reinterpret_cast<const float4*>(x)[i];
    __nv_bfloat16 h0, h1, h2, h3, l0, l1, l2, l3;
    split_bf16(v.x, h0, l0); split_bf16(v.y, h1, l1);
    split_bf16(v.z, h2, l2); split_bf16(v.w, h3, l3);
    __nv_bfloat162* ph = reinterpret_cast<__nv_bfloat162*>(xh) + 2 * i;
    __nv_bfloat162* pl = reinterpret_cast<__nv_bfloat162*>(xl) + 2 * i;
    __nv_bfloat162 a; a.x = h0; a.y = h1; ph[0] = a;
    __nv_bfloat162 b; b.x = h2; b.y = h3; ph[1] = b;
    __nv_bfloat162 c; c.x = l0; c.y = l1; pl[0] = c;
    __nv_bfloat162 d; d.x = l2; d.y = l3; pl[1] = d;
}

__global__ void convert_w_kernel(const float* __restrict__ W,
                                 __nv_bfloat16* __restrict__ Oh,
                                 __nv_bfloat16* __restrict__ Ol,
                                 int K, int N, size_t wStride, size_t oStride) {
    __shared__ float t[32][33];
    const float* Wb = W + (size_t)blockIdx.z * wStride;
    __nv_bfloat16* oh = Oh + (size_t)blockIdx.z * oStride;
    __nv_bfloat16* ol = Ol + (size_t)blockIdx.z * oStride;
    int k0 = blockIdx.y * 32, n0 = blockIdx.x * 32;
    int tx = threadIdx.x, ty = threadIdx.y;
#pragma unroll
    for (int j = 0; j < 4; j++)
        t[ty + 8 * j][tx] = Wb[(size_t)(k0 + ty + 8 * j) * N + n0 + tx];
    __syncthreads();
#pragma unroll
    for (int j = 0; j < 4; j++) {
        int r = ty + 8 * j;
        float v = t[tx][r];
        __nv_bfloat16 hi, lo; split_bf16(v, hi, lo);
        size_t o = (size_t)(n0 + r) * K + k0 + tx;
        oh[o] = hi; ol[o] = lo;
    }
}

// ---------------------------------------------------------------------------
// Gather-GEMM, 128x256 CTA tile, warp tile 64x64, 8 warps, 1 CTA/SM.
// MODE 1: t = (x @ w1[e]) * mw   (grid 1 x MAXT1, N=256 covers expert)
// MODE 2: h = gelu(t @ w2slice)  (grid 16 x MAXT2, K=512 pair-gathered)
// MODE 3: out = h @ lin2 + b     (grid 4 x 64, dense)
// ---------------------------------------------------------------------------
template <int MODE>
__global__ void __launch_bounds__(NTHREADS, 1)
mma_gemm(const float* __restrict__ bias, float* __restrict__ Cf) {
    __shared__ int ts[128];
    __shared__ float smw[128];
    extern __shared__ char smem[];
    const uint32_t sbase = s2u(smem);
    const int tid = threadIdx.x;
    const int lane = tid & 31;
    const int wid = tid >> 5;
    const int wm = wid & 1;           // 2 warps over M (64 rows)
    const int wn = wid >> 1;          // 4 warps over N (64 cols)

    int nrows = 128;
    int e = 0, e0 = 0, e1 = 0;
    if (MODE == 1) {
        if ((int)blockIdx.y >= g_meta[0]) return;
        e = g_t1grp[blockIdx.y];
        int r0 = g_t1row[blockIdx.y];
        nrows = min(128, g_ecnt[e] - r0);
        if (tid < 128) {
            int idx = g_eoff[e] + r0 + ((tid < nrows) ? tid : 0);
            int tk = g_etok[idx];
            ts[tid] = tk;
            smw[tid] = g_mw[tk * NE + e];
        }
    } else if (MODE == 2) {
        if ((int)blockIdx.y >= g_meta[1]) return;
        int p = g_t2grp[blockIdx.y];
        int r0 = g_t2row[blockIdx.y];
        nrows = min(128, g_pcnt[p] - r0);
        e0 = g_pe0[p]; e1 = g_pe1[p];
        if (tid < 128)
            ts[tid] = g_ptok[g_poff[p] + r0 + ((tid < nrows) ? tid : 0)];
    } else {
        if (tid < 128) ts[tid] = blockIdx.y * 128 + tid;
    }
    __syncthreads();

    const __nv_bfloat16 *Ahp, *Alp, *Bhp, *Blp;
    int ldA, ldB, brow0, NC;
    if (MODE == 1) {
        Ahp = g_xh; Alp = g_xl; ldA = HID;
        Bhp = g_w1h; Blp = g_w1l; ldB = HID;
        brow0 = e * 256;
        NC = HID / 32;
    } else if (MODE == 2) {
        Ahp = g_th; Alp = g_tl; ldA = ERK;
        Bhp = g_w2h; Blp = g_w2l; ldB = ERK;
        brow0 = blockIdx.x * 256;
        NC = 512 / 32;
    } else {
        Ahp = g_hh; Alp = g_hl; ldA = FFN;
        Bhp = g_w3h; Blp = g_w3l; ldB = FFN;
        brow0 = blockIdx.x * 256;
        NC = FFN / 32;
    }

    const int r0s = tid >> 2, q0 = tid & 3;          // r0s 0..63
    const size_t aoff0 = (size_t)ts[r0s] * ldA;
    const size_t aoff1 = (size_t)ts[r0s + 64] * ldA;
    size_t boff[4];
#pragma unroll
    for (int t4 = 0; t4 < 4; t4++)
        boff[t4] = (size_t)(brow0 + r0s + 64 * t4) * ldB;

    float acc[4][8][4];
#pragma unroll
    for (int i = 0; i < 4; i++)
#pragma unroll
        for (int j = 0; j < 8; j++)
#pragma unroll
            for (int k = 0; k < 4; k++) acc[i][j][k] = 0.f;

    auto kseg = [&](int c) -> size_t {
        if (MODE == 2)
            return (c < 8) ? (size_t)e0 * 256 + (size_t)c * 32
                           : (size_t)e1 * 256 + (size_t)(c - 8) * 32;
        return (size_t)c * 32;
    };

    auto load_chunk = [&](int c, int st) {
        const size_t ko = kseg(c) + (size_t)q0 * 8;
        const uint32_t s = sbase + (uint32_t)st * STG;
        // A: rows r0s and r0s+64
        uint32_t d0 = s + (uint32_t)(r0s * ROWB + q0 * 16);
        uint32_t d1 = d0 + (uint32_t)(64 * ROWB);
        cp16(d0,          Ahp + aoff0 + ko);
        cp16(d0 + A_T,    Alp + aoff0 + ko);
        cp16(d1,          Ahp + aoff1 + ko);
        cp16(d1 + A_T,    Alp + aoff1 + ko);
        // B: rows r0s + 64t
        const uint32_t bb = s + (uint32_t)(2 * A_T);
#pragma unroll
        for (int t4 = 0; t4 < 4; t4++) {
            uint32_t db = bb + (uint32_t)((r0s + 64 * t4) * ROWB + q0 * 16);
            cp16(db,        Bhp + boff[t4] + ko);
            cp16(db + B_T,  Blp + boff[t4] + ko);
        }
        cp_commit();
    };

    load_chunk(0, 0);

    const int g = lane >> 3, lr = lane & 7;

    for (int c = 0; c < NC; c++) {
        cp_wait<0>();
        __syncthreads();
        if (c + 1 < NC) load_chunk(c + 1, (c + 1) & 1);

        const uint32_t s0 = sbase + (uint32_t)((c & 1) * STG);
#pragma unroll
        for (int ks = 0; ks < 2; ks++) {
            uint32_t afh[4][4], afl[4][4];
#pragma unroll
            for (int mt = 0; mt < 4; mt++) {
                int row = wm * 64 + mt * 16 + (g & 1) * 8 + lr;
                uint32_t addr = s0 + (uint32_t)(row * ROWB + ks * 32 + (g >> 1) * 16);
                ldsm4(afh[mt], addr);
                ldsm4(afl[mt], addr + A_T);
            }
#pragma unroll
            for (int np = 0; np < 4; np++) {
                uint32_t bfh[4], bfl[4];
                int row = wn * 64 + np * 16 + (g >> 1) * 8 + lr;
                uint32_t addr = s0 + (uint32_t)(2 * A_T + row * ROWB + ks * 32 + (g & 1) * 16);
                ldsm4(bfh, addr);
                ldsm4(bfl, addr + B_T);
#pragma unroll
                for (int mt = 0; mt < 4; mt++) {
#pragma unroll
                    for (int h2 = 0; h2 < 2; h2++) {
                        float* cc = acc[mt][np * 2 + h2];
                        mma16816(cc, afh[mt], bfh + h2 * 2);
                        mma16816(cc, afh[mt], bfl + h2 * 2);
                        mma16816(cc, afl[mt], bfh + h2 * 2);
                    }
                }
            }
        }
    }

    // Epilogue
#pragma unroll
    for (int mt = 0; mt < 4; mt++) {
#pragma unroll
        for (int half = 0; half < 2; half++) {
            const int rl = wm * 64 + mt * 16 + half * 8 + (lane >> 2);
            const bool valid = rl < nrows;
            const int tok = ts[rl];
            float s = 1.f;
            if (MODE == 1) s = smw[rl];
            size_t rbase;
            if (MODE == 1)      rbase = (size_t)tok * ERK + e * 256;
            else if (MODE == 2) rbase = (size_t)tok * FFN + blockIdx.x * 256;
            else                rbase = (size_t)tok * HID + blockIdx.x * 256;
#pragma unroll
            for (int nt = 0; nt < 8; nt++) {
                const int col = wn * 64 + nt * 8 + (lane & 3) * 2;
                float v0 = acc[mt][nt][half * 2 + 0];
                float v1 = acc[mt][nt][half * 2 + 1];
                if (MODE == 3) {
                    if (valid) {
                        float2 o;
                        o.x = v0 + bias[blockIdx.x * 256 + col];
                        o.y = v1 + bias[blockIdx.x * 256 + col + 1];
                        *reinterpret_cast<float2*>(Cf + rbase + col) = o;
                    }
                } else {
                    if (MODE == 1) { v0 *= s; v1 *= s; }
                    else {
                        v0 = 0.5f * v0 * (1.f + erff(v0 * 0.70710678118654752f));
                        v1 = 0.5f * v1 * (1.f + erff(v1 * 0.70710678118654752f));
                    }
                    if (valid) {
                        __nv_bfloat16 h0, h1, l0, l1;
                        split_bf16(v0, h0, l0); split_bf16(v1, h1, l1);
                        __nv_bfloat162 hp; hp.x = h0; hp.y = h1;
                        __nv_bfloat162 lp; lp.x = l0; lp.y = l1;
                        __nv_bfloat16* Ch = (MODE == 1) ? g_th : g_hh;
                        __nv_bfloat16* Cl = (MODE == 1) ? g_tl : g_hl;
                        *reinterpret_cast<__nv_bfloat162*>(Ch + rbase + col) = hp;
                        *reinterpret_cast<__nv_bfloat162*>(Cl + rbase + col) = lp;
                    }
                }
            }
        }
    }
}

// ---------------------------------------------------------------------------
extern "C" void kernel_launch(void* const* d_in, const int* in_sizes, int n_in,
                              void* d_out, int out_size) {
    const float* x        = (const float*)d_in[0];
    const float* router_w = (const float*)d_in[1];
    const float* router_b = (const float*)d_in[2];
    const float* w1       = (const float*)d_in[3];
    const float* w2       = (const float*)d_in[4];
    const float* lin2_w   = (const float*)d_in[5];
    const float* lin2_b   = (const float*)d_in[6];
    float* out = (float*)d_out;

    __nv_bfloat16 *xh, *xl, *w1h, *w1l, *w2h, *w2l, *w3h, *w3l;
    cudaGetSymbolAddress((void**)&xh, g_xh);   cudaGetSymbolAddress((void**)&xl, g_xl);
    cudaGetSymbolAddress((void**)&w1h, g_w1h); cudaGetSymbolAddress((void**)&w1l, g_w1l);
    cudaGetSymbolAddress((void**)&w2h, g_w2h); cudaGetSymbolAddress((void**)&w2l, g_w2l);
    cudaGetSymbolAddress((void**)&w3h, g_w3h); cudaGetSymbolAddress((void**)&w3l, g_w3l);

    cudaFuncSetAttribute(mma_gemm<1>, cudaFuncAttributeMaxDynamicSharedMemorySize, SMEM_BYTES);
    cudaFuncSetAttribute(mma_gemm<2>, cudaFuncAttributeMaxDynamicSharedMemorySize, SMEM_BYTES);
    cudaFuncSetAttribute(mma_gemm<3>, cudaFuncAttributeMaxDynamicSharedMemorySize, SMEM_BYTES);

    // Routing metadata
    zero_kernel<<<1, 32>>>();
    router_kernel<<<TOK / 8, 256>>>(x, router_w, router_b);
    plan_kernel<<<1, 32>>>();
    scatter_kernel<<<TOK / 256, 256>>>();

    // Conversions
    convert_x_kernel<<<(TOK * HID / 4) / 256, 256>>>(x, xh, xl);
    convert_w_kernel<<<dim3(RNK / 32, HID / 32, NE), dim3(32, 8)>>>(
        w1, w1h, w1l, HID, RNK, (size_t)HID * RNK, (size_t)RNK * HID);
    convert_w_kernel<<<dim3(FFN / 32, ERK / 32, 1), dim3(32, 8)>>>(
        w2, w2h, w2l, ERK, FFN, 0, 0);
    convert_w_kernel<<<dim3(HID / 32, FFN / 32, 1), dim3(32, 8)>>>(
        lin2_w, w3h, w3l, FFN, HID, 0, 0);

    // Stage 1 (sparse, per-expert, N=256): t = (x @ w1[e]) * mw
    mma_gemm<1><<<dim3(1, MAXT1), NTHREADS, SMEM_BYTES>>>(nullptr, nullptr);
    // Stage 2 (sparse, per-pair, K=512): h = gelu(t @ w2)
    mma_gemm<2><<<dim3(FFN / 256, MAXT2), NTHREADS, SMEM_BYTES>>>(nullptr, nullptr);
    // Stage 3 (dense): out = h @ lin2 + b
    mma_gemm<3><<<dim3(HID / 256, TOK / 128), NTHREADS, SMEM_BYTES>>>(lin2_b, out);
}

// round 11
// speedup vs baseline: 1.0649x; 1.0649x over previous
#include <cuda_runtime.h>
#include <cuda_bf16.h>
#include <stdint.h>
#include <math.h>

#define TOK 8192
#define HID 1024
#define RNK 256
#define FFN 4096
#define NE  8
#define ERK (NE*RNK)  // 2048
#define NPAIR 28
#define MAXT1 136
#define MAXT2 92

#define NTHREADS 512
#define ROWB 80
#define A_T (128*ROWB)            // 10240
#define B_T (256*ROWB)            // 20480
#define STG (2*A_T + 2*B_T)       // 61440
#define SMEM_BYTES (2*STG)        // 122880

// ---------------------------------------------------------------------------
// Scratch (device globals)
// ---------------------------------------------------------------------------
__device__ float g_mw[TOK * NE];
__device__ int g_e0t[TOK], g_e1t[TOK], g_pidt[TOK];
__device__ int g_pcnt[NPAIR], g_poff[NPAIR], g_pfill[NPAIR], g_ptok[TOK];
__device__ int g_ecnt[NE], g_eoff[NE], g_efill[NE], g_etok[2 * TOK];
__device__ int g_t1grp[MAXT1], g_t1row[MAXT1];
__device__ int g_t2grp[MAXT2], g_t2row[MAXT2];
__device__ int g_pe0[NPAIR], g_pe1[NPAIR];
__device__ int g_meta[2];

__device__ __nv_bfloat16 g_xh[(size_t)TOK * HID], g_xl[(size_t)TOK * HID];
__device__ __nv_bfloat16 g_th[(size_t)TOK * ERK], g_tl[(size_t)TOK * ERK];
__device__ __nv_bfloat16 g_hh[(size_t)TOK * FFN], g_hl[(size_t)TOK * FFN];
__device__ __nv_bfloat16 g_w1h[(size_t)ERK * HID], g_w1l[(size_t)ERK * HID];
__device__ __nv_bfloat16 g_w2h[(size_t)FFN * ERK], g_w2l[(size_t)FFN * ERK];
__device__ __nv_bfloat16 g_w3h[(size_t)HID * FFN], g_w3l[(size_t)HID * FFN];

// ---------------------------------------------------------------------------
// PTX helpers (base sm_103 target)
// ---------------------------------------------------------------------------
__device__ __forceinline__ uint32_t s2u(const void* p) {
    uint32_t a;
    asm("{ .reg .u64 t; cvta.to.shared.u64 t, %1; cvt.u32.u64 %0, t; }" : "=r"(a) : "l"(p));
    return a;
}
__device__ __forceinline__ void cp16(uint32_t dst, const void* src) {
    asm volatile("cp.async.cg.shared.global [%0], [%1], 16;" :: "r"(dst), "l"(src) : "memory");
}
__device__ __forceinline__ void cp_commit() {
    asm volatile("cp.async.commit_group;" ::: "memory");
}
template <int N>
__device__ __forceinline__ void cp_wait() {
    asm volatile("cp.async.wait_group %0;" :: "n"(N) : "memory");
}
__device__ __forceinline__ void ldsm4(uint32_t* r, uint32_t addr) {
    asm volatile("ldmatrix.sync.aligned.m8n8.x4.shared.b16 {%0,%1,%2,%3}, [%4];"
                 : "=r"(r[0]), "=r"(r[1]), "=r"(r[2]), "=r"(r[3]) : "r"(addr));
}
__device__ __forceinline__ void mma16816(float* c, const uint32_t* a, const uint32_t* b) {
    asm volatile(
        "mma.sync.aligned.m16n8k16.row.col.f32.bf16.bf16.f32 "
        "{%0,%1,%2,%3}, {%4,%5,%6,%7}, {%8,%9}, {%0,%1,%2,%3};"
        : "+f"(c[0]), "+f"(c[1]), "+f"(c[2]), "+f"(c[3])
        : "r"(a[0]), "r"(a[1]), "r"(a[2]), "r"(a[3]), "r"(b[0]), "r"(b[1]));
}
__device__ __forceinline__ void split_bf16(float v, __nv_bfloat16& hi, __nv_bfloat16& lo) {
    hi = __float2bfloat16(v);
    lo = __float2bfloat16(v - __bfloat162float(hi));
}

// ---------------------------------------------------------------------------
// Routing infrastructure
// ---------------------------------------------------------------------------
__global__ void zero_kernel() {
    int i = threadIdx.x;
    if (i < NPAIR) { g_pcnt[i] = 0; g_pfill[i] = 0; }
    if (i < NE)    { g_ecnt[i] = 0; g_efill[i] = 0; }
}

__global__ void router_kernel(const float* __restrict__ x,
                              const float* __restrict__ rw,
                              const float* __restrict__ rb) {
    int warp = (blockIdx.x * blockDim.x + threadIdx.x) >> 5;
    int lane = threadIdx.x & 31;
    if (warp >= TOK) return;

    const float4* xr = reinterpret_cast<const float4*>(x + (size_t)warp * HID);
    float acc[NE];
#pragma unroll
    for (int e = 0; e < NE; e++) acc[e] = 0.f;

    for (int i = lane; i < HID / 4; i += 32) {
        float4 xv = xr[i];
        int h = i * 4;
        const float4* w0 = reinterpret_cast<const float4*>(rw + (size_t)h * NE);
        float4 a0 = w0[0], a1 = w0[1];
        float4 b0 = w0[2], b1 = w0[3];
        float4 c0 = w0[4], c1 = w0[5];
        float4 d0 = w0[6], d1 = w0[7];
        acc[0] += xv.x*a0.x + xv.y*b0.x + xv.z*c0.x + xv.w*d0.x;
        acc[1] += xv.x*a0.y + xv.y*b0.y + xv.z*c0.y + xv.w*d0.y;
        acc[2] += xv.x*a0.z + xv.y*b0.z + xv.z*c0.z + xv.w*d0.z;
        acc[3] += xv.x*a0.w + xv.y*b0.w + xv.z*c0.w + xv.w*d0.w;
        acc[4] += xv.x*a1.x + xv.y*b1.x + xv.z*c1.x + xv.w*d1.x;
        acc[5] += xv.x*a1.y + xv.y*b1.y + xv.z*c1.y + xv.w*d1.y;
        acc[6] += xv.x*a1.z + xv.y*b1.z + xv.z*c1.z + xv.w*d1.z;
        acc[7] += xv.x*a1.w + xv.y*b1.w + xv.z*c1.w + xv.w*d1.w;
    }
#pragma unroll
    for (int e = 0; e < NE; e++) {
#pragma unroll
        for (int o = 16; o > 0; o >>= 1)
            acc[e] += __shfl_xor_sync(0xffffffffu, acc[e], o);
    }
    if (lane == 0) {
        float lg[NE], m = -1e30f;
#pragma unroll
        for (int e = 0; e < NE; e++) { lg[e] = acc[e] + rb[e]; m = fmaxf(m, lg[e]); }
        float p[NE], s = 0.f;
#pragma unroll
        for (int e = 0; e < NE; e++) { p[e] = expf(lg[e] - m); s += p[e]; }
        float inv = 1.f / s;
        int i0 = 0;
#pragma unroll
        for (int e = 1; e < NE; e++) if (p[e] > p[i0]) i0 = e;
        int i1 = (i0 == 0) ? 1 : 0;
#pragma unroll
        for (int e = 0; e < NE; e++) { if (e == i0) continue; if (p[e] > p[i1]) i1 = e; }
#pragma unroll
        for (int e = 0; e < NE; e++)
            g_mw[warp * NE + e] = (e == i0 || e == i1) ? p[e] * inv : 0.f;
        int e0 = min(i0, i1), e1 = max(i0, i1);
        int pid = e0 * (2 * NE - e0 - 1) / 2 + (e1 - e0 - 1);
        g_e0t[warp] = e0; g_e1t[warp] = e1; g_pidt[warp] = pid;
        atomicAdd(&g_pcnt[pid], 1);
        atomicAdd(&g_ecnt[e0], 1);
        atomicAdd(&g_ecnt[e1], 1);
    }
}

__global__ void plan_kernel() {
    __shared__ int sec[NE], spc[NPAIR];
    int lane = threadIdx.x;
    if (lane < NE) sec[lane] = g_ecnt[lane];
    if (lane < NPAIR) spc[lane] = g_pcnt[lane];
    __syncwarp();
    if (lane != 0) return;
    int off = 0, nt = 0;
    for (int e = 0; e < NE; e++) {
        g_eoff[e] = off;
        for (int r = 0; r < sec[e]; r += 128) { g_t1grp[nt] = e; g_t1row[nt] = r; nt++; }
        off += sec[e];
    }
    g_meta[0] = nt;
    off = 0; nt = 0;
    int p = 0;
    for (int a = 0; a < NE; a++)
        for (int b = a + 1; b < NE; b++) {
            g_pe0[p] = a; g_pe1[p] = b;
            g_poff[p] = off;
            for (int r = 0; r < spc[p]; r += 128) { g_t2grp[nt] = p; g_t2row[nt] = r; nt++; }
            off += spc[p];
            p++;
        }
    g_meta[1] = nt;
}

__global__ void scatter_kernel() {
    int t = blockIdx.x * blockDim.x + threadIdx.x;
    if (t >= TOK) return;
    int pid = g_pidt[t];
    int pos = atomicAdd(&g_pfill[pid], 1);
    g_ptok[g_poff[pid] + pos] = t;
    int e0 = g_e0t[t], e1 = g_e1t[t];
    pos = atomicAdd(&g_efill[e0], 1); g_etok[g_eoff[e0] + pos] = t;
    pos = atomicAdd(&g_efill[e1], 1); g_etok[g_eoff[e1] + pos] = t;
}

// ---------------------------------------------------------------------------
// Conversions
// ---------------------------------------------------------------------------
__global__ void convert_x_kernel(const float* __restrict__ x,
                                 __nv_bfloat16* __restrict__ xh,
                                 __nv_bfloat16* __restrict__ xl) {
    size_t i = (size_t)blockIdx.x * blockDim.x + threadIdx.x;
    float4 v = reinterpret_cast<const float4*>(x)[i];
    __nv_bfloat16 h0, h1, h2, h3, l0, l1, l2, l3;
    split_bf16(v.x, h0, l0); split_bf16(v.y, h1, l1);
    split_bf16(v.z, h2, l2); split_bf16(v.w, h3, l3);
    __nv_bfloat162* ph = reinterpret_cast<__nv_bfloat162*>(xh) + 2 * i;
    __nv_bfloat162* pl = reinterpret_cast<__nv_bfloat162*>(xl) + 2 * i;
    __nv_bfloat162 a; a.x = h0; a.y = h1; ph[0] = a;
    __nv_bfloat162 b; b.x = h2; b.y = h3; ph[1] = b;
    __nv_bfloat162 c; c.x = l0; c.y = l1; pl[0] = c;
    __nv_bfloat162 d; d.x = l2; d.y = l3; pl[1] = d;
}

__global__ void convert_w_kernel(const float* __restrict__ W,
                                 __nv_bfloat16* __restrict__ Oh,
                                 __nv_bfloat16* __restrict__ Ol,
                                 int K, int N, size_t wStride, size_t oStride) {
    __shared__ float t[32][33];
    const float* Wb = W + (size_t)blockIdx.z * wStride;
    __nv_bfloat16* oh = Oh + (size_t)blockIdx.z * oStride;
    __nv_bfloat16* ol = Ol + (size_t)blockIdx.z * oStride;
    int k0 = blockIdx.y * 32, n0 = blockIdx.x * 32;
    int tx = threadIdx.x, ty = threadIdx.y;
#pragma unroll
    for (int j = 0; j < 4; j++)
        t[ty + 8 * j][tx] = Wb[(size_t)(k0 + ty + 8 * j) * N + n0 + tx];
    __syncthreads();
#pragma unroll
    for (int j = 0; j < 4; j++) {
        int r = ty + 8 * j;
        float v = t[tx][r];
        __nv_bfloat16 hi, lo; split_bf16(v, hi, lo);
        size_t o = (size_t)(n0 + r) * K + k0 + tx;
        oh[o] = hi; ol[o] = lo;
    }
}

// ---------------------------------------------------------------------------
// Gather-GEMM, 128x256 CTA tile, 512 threads (16 warps), warp tile 32x64.
// 4 warps over M (32 rows each) x 4 warps over N (64 cols each).
// MODE 1: t = (x @ w1[e]) * mw   (grid 1 x MAXT1)
// MODE 2: h = gelu(t @ w2slice)  (grid 16 x MAXT2, K=512 pair-gathered)
// MODE 3: out = h @ lin2 + b     (grid 4 x 64, dense)
// ---------------------------------------------------------------------------
template <int MODE>
__global__ void __launch_bounds__(NTHREADS, 1)
mma_gemm(const float* __restrict__ bias, float* __restrict__ Cf) {
    __shared__ int ts[128];
    __shared__ float smw[128];
    extern __shared__ char smem[];
    const uint32_t sbase = s2u(smem);
    const int tid = threadIdx.x;
    const int lane = tid & 31;
    const int wid = tid >> 5;
    const int wm = wid & 3;           // 4 warps over M (32 rows each)
    const int wn = wid >> 2;          // 4 warps over N (64 cols each)

    int nrows = 128;
    int e = 0, e0 = 0, e1 = 0;
    if (MODE == 1) {
        if ((int)blockIdx.y >= g_meta[0]) return;
        e = g_t1grp[blockIdx.y];
        int r0 = g_t1row[blockIdx.y];
        nrows = min(128, g_ecnt[e] - r0);
        if (tid < 128) {
            int idx = g_eoff[e] + r0 + ((tid < nrows) ? tid : 0);
            int tk = g_etok[idx];
            ts[tid] = tk;
            smw[tid] = g_mw[tk * NE + e];
        }
    } else if (MODE == 2) {
        if ((int)blockIdx.y >= g_meta[1]) return;
        int p = g_t2grp[blockIdx.y];
        int r0 = g_t2row[blockIdx.y];
        nrows = min(128, g_pcnt[p] - r0);
        e0 = g_pe0[p]; e1 = g_pe1[p];
        if (tid < 128)
            ts[tid] = g_ptok[g_poff[p] + r0 + ((tid < nrows) ? tid : 0)];
    } else {
        if (tid < 128) ts[tid] = blockIdx.y * 128 + tid;
    }
    __syncthreads();

    const __nv_bfloat16 *Ahp, *Alp, *Bhp, *Blp;
    int ldA, ldB, brow0, NC;
    if (MODE == 1) {
        Ahp = g_xh; Alp = g_xl; ldA = HID;
        Bhp = g_w1h; Blp = g_w1l; ldB = HID;
        brow0 = e * 256;
        NC = HID / 32;
    } else if (MODE == 2) {
        Ahp = g_th; Alp = g_tl; ldA = ERK;
        Bhp = g_w2h; Blp = g_w2l; ldB = ERK;
        brow0 = blockIdx.x * 256;
        NC = 512 / 32;
    } else {
        Ahp = g_hh; Alp = g_hl; ldA = FFN;
        Bhp = g_w3h; Blp = g_w3l; ldB = FFN;
        brow0 = blockIdx.x * 256;
        NC = FFN / 32;
    }

    const int r0s = tid >> 2, q0 = tid & 3;          // r0s 0..127
    const size_t aoff0 = (size_t)ts[r0s] * ldA;      // A row r0s
    const size_t boff0 = (size_t)(brow0 + r0s) * ldB;
    const size_t boff1 = (size_t)(brow0 + r0s + 128) * ldB;

    float acc[2][8][4];
#pragma unroll
    for (int i = 0; i < 2; i++)
#pragma unroll
        for (int j = 0; j < 8; j++)
#pragma unroll
            for (int k = 0; k < 4; k++) acc[i][j][k] = 0.f;

    auto kseg = [&](int c) -> size_t {
        if (MODE == 2)
            return (c < 8) ? (size_t)e0 * 256 + (size_t)c * 32
                           : (size_t)e1 * 256 + (size_t)(c - 8) * 32;
        return (size_t)c * 32;
    };

    auto load_chunk = [&](int c, int st) {
        const size_t ko = kseg(c) + (size_t)q0 * 8;
        const uint32_t s = sbase + (uint32_t)st * STG;
        // A: 128 rows, one per thread-group
        uint32_t da = s + (uint32_t)(r0s * ROWB + q0 * 16);
        cp16(da,        Ahp + aoff0 + ko);
        cp16(da + A_T,  Alp + aoff0 + ko);
        // B: 256 rows (r0s, r0s+128)
        const uint32_t bb = s + (uint32_t)(2 * A_T);
        uint32_t db0 = bb + (uint32_t)(r0s * ROWB + q0 * 16);
        uint32_t db1 = db0 + (uint32_t)(128 * ROWB);
        cp16(db0,       Bhp + boff0 + ko);
        cp16(db0 + B_T, Blp + boff0 + ko);
        cp16(db1,       Bhp + boff1 + ko);
        cp16(db1 + B_T, Blp + boff1 + ko);
        cp_commit();
    };

    load_chunk(0, 0);

    const int g = lane >> 3, lr = lane & 7;

    for (int c = 0; c < NC; c++) {
        cp_wait<0>();
        __syncthreads();
        if (c + 1 < NC) load_chunk(c + 1, (c + 1) & 1);

        const uint32_t s0 = sbase + (uint32_t)((c & 1) * STG);
#pragma unroll
        for (int ks = 0; ks < 2; ks++) {
            uint32_t afh[2][4], afl[2][4];
#pragma unroll
            for (int mt = 0; mt < 2; mt++) {
                int row = wm * 32 + mt * 16 + (g & 1) * 8 + lr;
                uint32_t addr = s0 + (uint32_t)(row * ROWB + ks * 32 + (g >> 1) * 16);
                ldsm4(afh[mt], addr);
                ldsm4(afl[mt], addr + A_T);
            }
#pragma unroll
            for (int np = 0; np < 4; np++) {
                uint32_t bfh[4], bfl[4];
                int row = wn * 64 + np * 16 + (g >> 1) * 8 + lr;
                uint32_t addr = s0 + (uint32_t)(2 * A_T + row * ROWB + ks * 32 + (g & 1) * 16);
                ldsm4(bfh, addr);
                ldsm4(bfl, addr + B_T);
#pragma unroll
                for (int mt = 0; mt < 2; mt++) {
#pragma unroll
                    for (int h2 = 0; h2 < 2; h2++) {
                        float* cc = acc[mt][np * 2 + h2];
                        mma16816(cc, afh[mt], bfh + h2 * 2);
                        mma16816(cc, afh[mt], bfl + h2 * 2);
                        mma16816(cc, afl[mt], bfh + h2 * 2);
                    }
                }
            }
        }
    }

    // Epilogue
#pragma unroll
    for (int mt = 0; mt < 2; mt++) {
#pragma unroll
        for (int half = 0; half < 2; half++) {
            const int rl = wm * 32 + mt * 16 + half * 8 + (lane >> 2);
            const bool valid = rl < nrows;
            const int tok = ts[rl];
            float s = 1.f;
            if (MODE == 1) s = smw[rl];
            size_t rbase;
            if (MODE == 1)      rbase = (size_t)tok * ERK + e * 256;
            else if (MODE == 2) rbase = (size_t)tok * FFN + blockIdx.x * 256;
            else                rbase = (size_t)tok * HID + blockIdx.x * 256;
#pragma unroll
            for (int nt = 0; nt < 8; nt++) {
                const int col = wn * 64 + nt * 8 + (lane & 3) * 2;
                float v0 = acc[mt][nt][half * 2 + 0];
                float v1 = acc[mt][nt][half * 2 + 1];
                if (MODE == 3) {
                    if (valid) {
                        float2 o;
                        o.x = v0 + bias[blockIdx.x * 256 + col];
                        o.y = v1 + bias[blockIdx.x * 256 + col + 1];
                        *reinterpret_cast<float2*>(Cf + rbase + col) = o;
                    }
                } else {
                    if (MODE == 1) { v0 *= s; v1 *= s; }
                    else {
                        v0 = 0.5f * v0 * (1.f + erff(v0 * 0.70710678118654752f));
                        v1 = 0.5f * v1 * (1.f + erff(v1 * 0.70710678118654752f));
                    }
                    if (valid) {
                        __nv_bfloat16 h0, h1, l0, l1;
                        split_bf16(v0, h0, l0); split_bf16(v1, h1, l1);
                        __nv_bfloat162 hp; hp.x = h0; hp.y = h1;
                        __nv_bfloat162 lp; lp.x = l0; lp.y = l1;
                        __nv_bfloat16* Ch = (MODE == 1) ? g_th : g_hh;
                        __nv_bfloat16* Cl = (MODE == 1) ? g_tl : g_hl;
                        *reinterpret_cast<__nv_bfloat162*>(Ch + rbase + col) = hp;
                        *reinterpret_cast<__nv_bfloat162*>(Cl + rbase + col) = lp;
                    }
                }
            }
        }
    }
}

// ---------------------------------------------------------------------------
extern "C" void kernel_launch(void* const* d_in, const int* in_sizes, int n_in,
                              void* d_out, int out_size) {
    const float* x        = (const float*)d_in[0];
    const float* router_w = (const float*)d_in[1];
    const float* router_b = (const float*)d_in[2];
    const float* w1       = (const float*)d_in[3];
    const float* w2       = (const float*)d_in[4];
    const float* lin2_w   = (const float*)d_in[5];
    const float* lin2_b   = (const float*)d_in[6];
    float* out = (float*)d_out;

    __nv_bfloat16 *xh, *xl, *w1h, *w1l, *w2h, *w2l, *w3h, *w3l;
    cudaGetSymbolAddress((void**)&xh, g_xh);   cudaGetSymbolAddress((void**)&xl, g_xl);
    cudaGetSymbolAddress((void**)&w1h, g_w1h); cudaGetSymbolAddress((void**)&w1l, g_w1l);
    cudaGetSymbolAddress((void**)&w2h, g_w2h); cudaGetSymbolAddress((void**)&w2l, g_w2l);
    cudaGetSymbolAddress((void**)&w3h, g_w3h); cudaGetSymbolAddress((void**)&w3l, g_w3l);

    cudaFuncSetAttribute(mma_gemm<1>, cudaFuncAttributeMaxDynamicSharedMemorySize, SMEM_BYTES);
    cudaFuncSetAttribute(mma_gemm<2>, cudaFuncAttributeMaxDynamicSharedMemorySize, SMEM_BYTES);
    cudaFuncSetAttribute(mma_gemm<3>, cudaFuncAttributeMaxDynamicSharedMemorySize, SMEM_BYTES);

    // Routing metadata
    zero_kernel<<<1, 32>>>();
    router_kernel<<<TOK / 8, 256>>>(x, router_w, router_b);
    plan_kernel<<<1, 32>>>();
    scatter_kernel<<<TOK / 256, 256>>>();

    // Conversions
    convert_x_kernel<<<(TOK * HID / 4) / 256, 256>>>(x, xh, xl);
    convert_w_kernel<<<dim3(RNK / 32, HID / 32, NE), dim3(32, 8)>>>(
        w1, w1h, w1l, HID, RNK, (size_t)HID * RNK, (size_t)RNK * HID);
    convert_w_kernel<<<dim3(FFN / 32, ERK / 32, 1), dim3(32, 8)>>>(
        w2, w2h, w2l, ERK, FFN, 0, 0);
    convert_w_kernel<<<dim3(HID / 32, FFN / 32, 1), dim3(32, 8)>>>(
        lin2_w, w3h, w3l, FFN, HID, 0, 0);

    // Stage 1 (sparse, per-expert, N=256): t = (x @ w1[e]) * mw
    mma_gemm<1><<<dim3(1, MAXT1), NTHREADS, SMEM_BYTES>>>(nullptr, nullptr);
    // Stage 2 (sparse, per-pair, K=512): h = gelu(t @ w2)
    mma_gemm<2><<<dim3(FFN / 256, MAXT2), NTHREADS, SMEM_BYTES>>>(nullptr, nullptr);
    // Stage 3 (dense): out = h @ lin2 + b
    mma_gemm<3><<<dim3(HID / 256, TOK / 128), NTHREADS, SMEM_BYTES>>>(lin2_b, out);
}

// round 12
// speedup vs baseline: 1.1176x; 1.0495x over previous
#include <cuda_runtime.h>
#include <cuda_bf16.h>
#include <stdint.h>
#include <math.h>

#define TOK 8192
#define HID 1024
#define RNK 256
#define FFN 4096
#define NE  8
#define ERK (NE*RNK)  // 2048
#define NPAIR 28
#define MAXT1 136
#define MAXT2 92

#define NTHREADS 512
#define ROWB 80
#define A_T (128*ROWB)            // 10240
#define B_T (256*ROWB)            // 20480
#define STG (2*A_T + 2*B_T)       // 61440
#define SMEM_BYTES (2*STG)        // 122880

// ---------------------------------------------------------------------------
// Scratch (device globals)
// ---------------------------------------------------------------------------
__device__ float g_mw[TOK * NE];
__device__ int g_e0t[TOK], g_e1t[TOK], g_pidt[TOK];
__device__ int g_pcnt[NPAIR], g_poff[NPAIR], g_pfill[NPAIR], g_ptok[TOK];
__device__ int g_ecnt[NE], g_eoff[NE], g_efill[NE], g_etok[2 * TOK];
__device__ int g_t1grp[MAXT1], g_t1row[MAXT1];
__device__ int g_t2grp[MAXT2], g_t2row[MAXT2];
__device__ int g_pe0[NPAIR], g_pe1[NPAIR];
__device__ int g_meta[2];

__device__ __nv_bfloat16 g_xh[(size_t)TOK * HID], g_xl[(size_t)TOK * HID];
__device__ __nv_bfloat16 g_th[(size_t)TOK * ERK], g_tl[(size_t)TOK * ERK];
__device__ __nv_bfloat16 g_hh[(size_t)TOK * FFN], g_hl[(size_t)TOK * FFN];
__device__ __nv_bfloat16 g_w1h[(size_t)ERK * HID], g_w1l[(size_t)ERK * HID];
__device__ __nv_bfloat16 g_w2h[(size_t)FFN * ERK], g_w2l[(size_t)FFN * ERK];
__device__ __nv_bfloat16 g_w3h[(size_t)HID * FFN], g_w3l[(size_t)HID * FFN];

// ---------------------------------------------------------------------------
// PTX helpers (base sm_103 target)
// ---------------------------------------------------------------------------
__device__ __forceinline__ uint32_t s2u(const void* p) {
    uint32_t a;
    asm("{ .reg .u64 t; cvta.to.shared.u64 t, %1; cvt.u32.u64 %0, t; }" : "=r"(a) : "l"(p));
    return a;
}
__device__ __forceinline__ void cp16(uint32_t dst, const void* src) {
    asm volatile("cp.async.cg.shared.global [%0], [%1], 16;" :: "r"(dst), "l"(src) : "memory");
}
__device__ __forceinline__ void cp_commit() {
    asm volatile("cp.async.commit_group;" ::: "memory");
}
template <int N>
__device__ __forceinline__ void cp_wait() {
    asm volatile("cp.async.wait_group %0;" :: "n"(N) : "memory");
}
__device__ __forceinline__ void ldsm4(uint32_t* r, uint32_t addr) {
    asm volatile("ldmatrix.sync.aligned.m8n8.x4.shared.b16 {%0,%1,%2,%3}, [%4];"
                 : "=r"(r[0]), "=r"(r[1]), "=r"(r[2]), "=r"(r[3]) : "r"(addr));
}
__device__ __forceinline__ void mma16816(float* c, const uint32_t* a, const uint32_t* b) {
    asm volatile(
        "mma.sync.aligned.m16n8k16.row.col.f32.bf16.bf16.f32 "
        "{%0,%1,%2,%3}, {%4,%5,%6,%7}, {%8,%9}, {%0,%1,%2,%3};"
        : "+f"(c[0]), "+f"(c[1]), "+f"(c[2]), "+f"(c[3])
        : "r"(a[0]), "r"(a[1]), "r"(a[2]), "r"(a[3]), "r"(b[0]), "r"(b[1]));
}
__device__ __forceinline__ void split_bf16(float v, __nv_bfloat16& hi, __nv_bfloat16& lo) {
    hi = __float2bfloat16(v);
    lo = __float2bfloat16(v - __bfloat162float(hi));
}

// ---------------------------------------------------------------------------
// Routing infrastructure
// ---------------------------------------------------------------------------
__global__ void zero_kernel() {
    int i = threadIdx.x;
    if (i < NPAIR) { g_pcnt[i] = 0; g_pfill[i] = 0; }
    if (i < NE)    { g_ecnt[i] = 0; g_efill[i] = 0; }
}

__global__ void router_kernel(const float* __restrict__ x,
                              const float* __restrict__ rw,
                              const float* __restrict__ rb) {
    int warp = (blockIdx.x * blockDim.x + threadIdx.x) >> 5;
    int lane = threadIdx.x & 31;
    if (warp >= TOK) return;

    const float4* xr = reinterpret_cast<const float4*>(x + (size_t)warp * HID);
    float acc[NE];
#pragma unroll
    for (int e = 0; e < NE; e++) acc[e] = 0.f;

    for (int i = lane; i < HID / 4; i += 32) {
        float4 xv = xr[i];
        int h = i * 4;
        const float4* w0 = reinterpret_cast<const float4*>(rw + (size_t)h * NE);
        float4 a0 = w0[0], a1 = w0[1];
        float4 b0 = w0[2], b1 = w0[3];
        float4 c0 = w0[4], c1 = w0[5];
        float4 d0 = w0[6], d1 = w0[7];
        acc[0] += xv.x*a0.x + xv.y*b0.x + xv.z*c0.x + xv.w*d0.x;
        acc[1] += xv.x*a0.y + xv.y*b0.y + xv.z*c0.y + xv.w*d0.y;
        acc[2] += xv.x*a0.z + xv.y*b0.z + xv.z*c0.z + xv.w*d0.z;
        acc[3] += xv.x*a0.w + xv.y*b0.w + xv.z*c0.w + xv.w*d0.w;
        acc[4] += xv.x*a1.x + xv.y*b1.x + xv.z*c1.x + xv.w*d1.x;
        acc[5] += xv.x*a1.y + xv.y*b1.y + xv.z*c1.y + xv.w*d1.y;
        acc[6] += xv.x*a1.z + xv.y*b1.z + xv.z*c1.z + xv.w*d1.z;
        acc[7] += xv.x*a1.w + xv.y*b1.w + xv.z*c1.w + xv.w*d1.w;
    }
#pragma unroll
    for (int e = 0; e < NE; e++) {
#pragma unroll
        for (int o = 16; o > 0; o >>= 1)
            acc[e] += __shfl_xor_sync(0xffffffffu, acc[e], o);
    }
    if (lane == 0) {
        float lg[NE], m = -1e30f;
#pragma unroll
        for (int e = 0; e < NE; e++) { lg[e] = acc[e] + rb[e]; m = fmaxf(m, lg[e]); }
        float p[NE], s = 0.f;
#pragma unroll
        for (int e = 0; e < NE; e++) { p[e] = expf(lg[e] - m); s += p[e]; }
        float inv = 1.f / s;
        int i0 = 0;
#pragma unroll
        for (int e = 1; e < NE; e++) if (p[e] > p[i0]) i0 = e;
        int i1 = (i0 == 0) ? 1 : 0;
#pragma unroll
        for (int e = 0; e < NE; e++) { if (e == i0) continue; if (p[e] > p[i1]) i1 = e; }
#pragma unroll
        for (int e = 0; e < NE; e++)
            g_mw[warp * NE + e] = (e == i0 || e == i1) ? p[e] * inv : 0.f;
        int e0 = min(i0, i1), e1 = max(i0, i1);
        int pid = e0 * (2 * NE - e0 - 1) / 2 + (e1 - e0 - 1);
        g_e0t[warp] = e0; g_e1t[warp] = e1; g_pidt[warp] = pid;
        atomicAdd(&g_pcnt[pid], 1);
        atomicAdd(&g_ecnt[e0], 1);
        atomicAdd(&g_ecnt[e1], 1);
    }
}

__global__ void plan_kernel() {
    __shared__ int sec[NE], spc[NPAIR];
    int lane = threadIdx.x;
    if (lane < NE) sec[lane] = g_ecnt[lane];
    if (lane < NPAIR) spc[lane] = g_pcnt[lane];
    __syncwarp();
    if (lane != 0) return;
    int off = 0, nt = 0;
    for (int e = 0; e < NE; e++) {
        g_eoff[e] = off;
        for (int r = 0; r < sec[e]; r += 128) { g_t1grp[nt] = e; g_t1row[nt] = r; nt++; }
        off += sec[e];
    }
    g_meta[0] = nt;
    off = 0; nt = 0;
    int p = 0;
    for (int a = 0; a < NE; a++)
        for (int b = a + 1; b < NE; b++) {
            g_pe0[p] = a; g_pe1[p] = b;
            g_poff[p] = off;
            for (int r = 0; r < spc[p]; r += 128) { g_t2grp[nt] = p; g_t2row[nt] = r; nt++; }
            off += spc[p];
            p++;
        }
    g_meta[1] = nt;
}

__global__ void scatter_kernel() {
    int t = blockIdx.x * blockDim.x + threadIdx.x;
    if (t >= TOK) return;
    int pid = g_pidt[t];
    int pos = atomicAdd(&g_pfill[pid], 1);
    g_ptok[g_poff[pid] + pos] = t;
    int e0 = g_e0t[t], e1 = g_e1t[t];
    pos = atomicAdd(&g_efill[e0], 1); g_etok[g_eoff[e0] + pos] = t;
    pos = atomicAdd(&g_efill[e1], 1); g_etok[g_eoff[e1] + pos] = t;
}

// ---------------------------------------------------------------------------
// Fused conversion kernel: x-split + 3 weight transposes in ONE launch
// grid.x = 8192 (x) + 2048 (w1) + 8192 (w2) + 4096 (w3) = 22528, block 256
// ---------------------------------------------------------------------------
__device__ __forceinline__ void transpose_tile(const float* __restrict__ W,
                                               __nv_bfloat16* __restrict__ oh,
                                               __nv_bfloat16* __restrict__ ol,
                                               int K, int N, int k0, int n0,
                                               float (*sm)[33]) {
    int tx = threadIdx.x & 31, ty = threadIdx.x >> 5;   // 32 x 8
#pragma unroll
    for (int j = 0; j < 4; j++)
        sm[ty + 8 * j][tx] = W[(size_t)(k0 + ty + 8 * j) * N + n0 + tx];
    __syncthreads();
#pragma unroll
    for (int j = 0; j < 4; j++) {
        int r = ty + 8 * j;
        float v = sm[tx][r];
        __nv_bfloat16 hi, lo; split_bf16(v, hi, lo);
        size_t o = (size_t)(n0 + r) * K + k0 + tx;
        oh[o] = hi; ol[o] = lo;
    }
}

__global__ void convert_all_kernel(const float* __restrict__ x,
                                   const float* __restrict__ w1,
                                   const float* __restrict__ w2,
                                   const float* __restrict__ w3) {
    __shared__ float sm[32][33];
    int b = blockIdx.x;
    if (b < 8192) {
        // x -> hi/lo split (float4 granularity)
        size_t i = (size_t)b * 256 + threadIdx.x;
        float4 v = reinterpret_cast<const float4*>(x)[i];
        __nv_bfloat16 h0, h1, h2, h3, l0, l1, l2, l3;
        split_bf16(v.x, h0, l0); split_bf16(v.y, h1, l1);
        split_bf16(v.z, h2, l2); split_bf16(v.w, h3, l3);
        __nv_bfloat162* ph = reinterpret_cast<__nv_bfloat162*>(g_xh) + 2 * i;
        __nv_bfloat162* pl = reinterpret_cast<__nv_bfloat162*>(g_xl) + 2 * i;
        __nv_bfloat162 a; a.x = h0; a.y = h1; ph[0] = a;
        __nv_bfloat162 bb; bb.x = h2; bb.y = h3; ph[1] = bb;
        __nv_bfloat162 c; c.x = l0; c.y = l1; pl[0] = c;
        __nv_bfloat162 d; d.x = l2; d.y = l3; pl[1] = d;
    } else if (b < 8192 + 2048) {
        int t2 = b - 8192;
        int e = t2 >> 8, r = t2 & 255;
        int bx = r & 7, by = r >> 3;                 // RNK/32=8, HID/32=32
        transpose_tile(w1 + (size_t)e * HID * RNK,
                       g_w1h + (size_t)e * RNK * HID,
                       g_w1l + (size_t)e * RNK * HID,
                       HID, RNK, by * 32, bx * 32, sm);
    } else if (b < 8192 + 2048 + 8192) {
        int t2 = b - 10240;
        int bx = t2 & 127, by = t2 >> 7;             // FFN/32=128, ERK/32=64
        transpose_tile(w2, g_w2h, g_w2l, ERK, FFN, by * 32, bx * 32, sm);
    } else {
        int t2 = b - 18432;
        int bx = t2 & 31, by = t2 >> 5;              // HID/32=32, FFN/32=128
        transpose_tile(w3, g_w3h, g_w3l, FFN, HID, by * 32, bx * 32, sm);
    }
}

// ---------------------------------------------------------------------------
// Gather-GEMM, 128x256 CTA tile, 512 threads (16 warps), warp tile 32x64.
// Software-pipelined fragments: 3-slot rotating B buffer, deferred cp.async.
// MODE 1: t = (x @ w1[e]) * mw   (grid 1 x MAXT1)
// MODE 2: h = gelu(t @ w2slice)  (grid 16 x MAXT2, K=512 pair-gathered)
// MODE 3: out = h @ lin2 + b     (grid 4 x 64, dense)
// ---------------------------------------------------------------------------
template <int MODE>
__global__ void __launch_bounds__(NTHREADS, 1)
mma_gemm(const float* __restrict__ bias, float* __restrict__ Cf) {
    __shared__ int ts[128];
    __shared__ float smw[128];
    extern __shared__ char smem[];
    const uint32_t sbase = s2u(smem);
    const int tid = threadIdx.x;
    const int lane = tid & 31;
    const int wid = tid >> 5;
    const int wm = wid & 3;           // 4 warps over M (32 rows each)
    const int wn = wid >> 2;          // 4 warps over N (64 cols each)

    int nrows = 128;
    int e = 0, e0 = 0, e1 = 0;
    if (MODE == 1) {
        if ((int)blockIdx.y >= g_meta[0]) return;
        e = g_t1grp[blockIdx.y];
        int r0 = g_t1row[blockIdx.y];
        nrows = min(128, g_ecnt[e] - r0);
        if (tid < 128) {
            int idx = g_eoff[e] + r0 + ((tid < nrows) ? tid : 0);
            int tk = g_etok[idx];
            ts[tid] = tk;
            smw[tid] = g_mw[tk * NE + e];
        }
    } else if (MODE == 2) {
        if ((int)blockIdx.y >= g_meta[1]) return;
        int p = g_t2grp[blockIdx.y];
        int r0 = g_t2row[blockIdx.y];
        nrows = min(128, g_pcnt[p] - r0);
        e0 = g_pe0[p]; e1 = g_pe1[p];
        if (tid < 128)
            ts[tid] = g_ptok[g_poff[p] + r0 + ((tid < nrows) ? tid : 0)];
    } else {
        if (tid < 128) ts[tid] = blockIdx.y * 128 + tid;
    }
    __syncthreads();

    const __nv_bfloat16 *Ahp, *Alp, *Bhp, *Blp;
    int ldA, ldB, brow0, NC;
    if (MODE == 1) {
        Ahp = g_xh; Alp = g_xl; ldA = HID;
        Bhp = g_w1h; Blp = g_w1l; ldB = HID;
        brow0 = e * 256;
        NC = HID / 32;
    } else if (MODE == 2) {
        Ahp = g_th; Alp = g_tl; ldA = ERK;
        Bhp = g_w2h; Blp = g_w2l; ldB = ERK;
        brow0 = blockIdx.x * 256;
        NC = 512 / 32;
    } else {
        Ahp = g_hh; Alp = g_hl; ldA = FFN;
        Bhp = g_w3h; Blp = g_w3l; ldB = FFN;
        brow0 = blockIdx.x * 256;
        NC = FFN / 32;
    }

    const int r0s = tid >> 2, q0 = tid & 3;          // r0s 0..127
    const size_t aoff0 = (size_t)ts[r0s] * ldA + q0 * 8;
    const size_t boff0 = (size_t)(brow0 + r0s) * ldB + q0 * 8;
    const size_t boff1 = (size_t)(brow0 + r0s + 128) * ldB + q0 * 8;

    // Hoisted cp.async source pointers + dst offsets
    const __nv_bfloat16 *pAh = Ahp + aoff0, *pAl = Alp + aoff0;
    const __nv_bfloat16 *pB0h = Bhp + boff0, *pB0l = Blp + boff0;
    const __nv_bfloat16 *pB1h = Bhp + boff1, *pB1l = Blp + boff1;
    const uint32_t dA  = (uint32_t)(r0s * ROWB + q0 * 16);
    const uint32_t dB0 = (uint32_t)(2 * A_T + r0s * ROWB + q0 * 16);
    const uint32_t dB1 = dB0 + (uint32_t)(128 * ROWB);

    float acc[2][8][4];
#pragma unroll
    for (int i = 0; i < 2; i++)
#pragma unroll
        for (int j = 0; j < 8; j++)
#pragma unroll
            for (int k = 0; k < 4; k++) acc[i][j][k] = 0.f;

    auto kseg = [&](int c) -> size_t {
        if (MODE == 2)
            return (c < 8) ? (size_t)e0 * 256 + (size_t)c * 32
                           : (size_t)e1 * 256 + (size_t)(c - 8) * 32;
        return (size_t)c * 32;
    };

    auto load_chunk = [&](int c, int st) {
        const size_t ko = kseg(c);
        const uint32_t s = sbase + (uint32_t)st * STG;
        cp16(s + dA,        pAh + ko);
        cp16(s + dA + A_T,  pAl + ko);
        cp16(s + dB0,       pB0h + ko);
        cp16(s + dB0 + B_T, pB0l + ko);
        cp16(s + dB1,       pB1h + ko);
        cp16(s + dB1 + B_T, pB1l + ko);
        cp_commit();
    };

    load_chunk(0, 0);

    const int g = lane >> 3, lr = lane & 7;
    // per-warp static ldsm offsets
    int aofs[2], bofs[4];
#pragma unroll
    for (int mt = 0; mt < 2; mt++)
        aofs[mt] = (wm * 32 + mt * 16 + (g & 1) * 8 + lr) * ROWB + (g >> 1) * 16;
#pragma unroll
    for (int np = 0; np < 4; np++)
        bofs[np] = (wn * 64 + np * 16 + (g >> 1) * 8 + lr) * ROWB + (g & 1) * 16;

    for (int c = 0; c < NC; c++) {
        cp_wait<0>();
        __syncthreads();
        const uint32_t sA = sbase + (uint32_t)((c & 1) * STG);
        const uint32_t sB = sA + (uint32_t)(2 * A_T);
        const bool have_next = (c + 1 < NC);

        uint32_t afh[2][4], afl[2][4];
        uint32_t bfh[3][4], bfl[3][4];   // 3-slot rotating buffer
#pragma unroll
        for (int mt = 0; mt < 2; mt++) {
            ldsm4(afh[mt], sA + aofs[mt]);
            ldsm4(afl[mt], sA + aofs[mt] + A_T);
        }
        ldsm4(bfh[0], sB + bofs[0]);
        ldsm4(bfl[0], sB + bofs[0] + B_T);

#pragma unroll
        for (int ks = 0; ks < 2; ks++) {
#pragma unroll
            for (int np = 0; np < 4; np++) {
                const int j = ks * 4 + np;
                const int cs = j % 3, ns = (j + 1) % 3;
                // prefetch next B group (next np, or ks=1 np=0)
                if (np < 3) {
                    ldsm4(bfh[ns], sB + bofs[np + 1] + ks * 32);
                    ldsm4(bfl[ns], sB + bofs[np + 1] + ks * 32 + B_T);
                } else if (ks == 0) {
                    ldsm4(bfh[ns], sB + bofs[0] + 32);
                    ldsm4(bfl[ns], sB + bofs[0] + 32 + B_T);
                }
#pragma unroll
                for (int mt = 0; mt < 2; mt++) {
#pragma unroll
                    for (int h2 = 0; h2 < 2; h2++) {
                        float* cc = acc[mt][np * 2 + h2];
                        mma16816(cc, afh[mt], bfh[cs] + h2 * 2);
                        mma16816(cc, afh[mt], bfl[cs] + h2 * 2);
                        mma16816(cc, afl[mt], bfh[cs] + h2 * 2);
                    }
                }
                // issue next chunk's cp.async after first MMA group
                if (ks == 0 && np == 0 && have_next) load_chunk(c + 1, (c + 1) & 1);
            }
            if (ks == 0) {
#pragma unroll
                for (int mt = 0; mt < 2; mt++) {
                    ldsm4(afh[mt], sA + aofs[mt] + 32);
                    ldsm4(afl[mt], sA + aofs[mt] + 32 + A_T);
                }
            }
        }
    }

    // Epilogue
#pragma unroll
    for (int mt = 0; mt < 2; mt++) {
#pragma unroll
        for (int half = 0; half < 2; half++) {
            const int rl = wm * 32 + mt * 16 + half * 8 + (lane >> 2);
            const bool valid = rl < nrows;
            const int tok = ts[rl];
            float s = 1.f;
            if (MODE == 1) s = smw[rl];
            size_t rbase;
            if (MODE == 1)      rbase = (size_t)tok * ERK + e * 256;
            else if (MODE == 2) rbase = (size_t)tok * FFN + blockIdx.x * 256;
            else                rbase = (size_t)tok * HID + blockIdx.x * 256;
#pragma unroll
            for (int nt = 0; nt < 8; nt++) {
                const int col = wn * 64 + nt * 8 + (lane & 3) * 2;
                float v0 = acc[mt][nt][half * 2 + 0];
                float v1 = acc[mt][nt][half * 2 + 1];
                if (MODE == 3) {
                    if (valid) {
                        float2 o;
                        o.x = v0 + bias[blockIdx.x * 256 + col];
                        o.y = v1 + bias[blockIdx.x * 256 + col + 1];
                        *reinterpret_cast<float2*>(Cf + rbase + col) = o;
                    }
                } else {
                    if (MODE == 1) { v0 *= s; v1 *= s; }
                    else {
                        v0 = 0.5f * v0 * (1.f + erff(v0 * 0.70710678118654752f));
                        v1 = 0.5f * v1 * (1.f + erff(v1 * 0.70710678118654752f));
                    }
                    if (valid) {
                        __nv_bfloat16 h0, h1, l0, l1;
                        split_bf16(v0, h0, l0); split_bf16(v1, h1, l1);
                        __nv_bfloat162 hp; hp.x = h0; hp.y = h1;
                        __nv_bfloat162 lp; lp.x = l0; lp.y = l1;
                        __nv_bfloat16* Ch = (MODE == 1) ? g_th : g_hh;
                        __nv_bfloat16* Cl = (MODE == 1) ? g_tl : g_hl;
                        *reinterpret_cast<__nv_bfloat162*>(Ch + rbase + col) = hp;
                        *reinterpret_cast<__nv_bfloat162*>(Cl + rbase + col) = lp;
                    }
                }
            }
        }
    }
}

// ---------------------------------------------------------------------------
extern "C" void kernel_launch(void* const* d_in, const int* in_sizes, int n_in,
                              void* d_out, int out_size) {
    const float* x        = (const float*)d_in[0];
    const float* router_w = (const float*)d_in[1];
    const float* router_b = (const float*)d_in[2];
    const float* w1       = (const float*)d_in[3];
    const float* w2       = (const float*)d_in[4];
    const float* lin2_w   = (const float*)d_in[5];
    const float* lin2_b   = (const float*)d_in[6];
    float* out = (float*)d_out;

    cudaFuncSetAttribute(mma_gemm<1>, cudaFuncAttributeMaxDynamicSharedMemorySize, SMEM_BYTES);
    cudaFuncSetAttribute(mma_gemm<2>, cudaFuncAttributeMaxDynamicSharedMemorySize, SMEM_BYTES);
    cudaFuncSetAttribute(mma_gemm<3>, cudaFuncAttributeMaxDynamicSharedMemorySize, SMEM_BYTES);

    // Launch order chosen so ncu (-s 5 -c 1) profiles mma_gemm<1> (launch idx 5)
    zero_kernel<<<1, 32>>>();                                       // 0
    router_kernel<<<TOK / 8, 256>>>(x, router_w, router_b);         // 1
    plan_kernel<<<1, 32>>>();                                       // 2
    scatter_kernel<<<TOK / 256, 256>>>();                           // 3
    convert_all_kernel<<<22528, 256>>>(x, w1, w2, lin2_w);          // 4

    // Stage 1 (sparse, per-expert, N=256): t = (x @ w1[e]) * mw
    mma_gemm<1><<<dim3(1, MAXT1), NTHREADS, SMEM_BYTES>>>(nullptr, nullptr);   // 5
    // Stage 2 (sparse, per-pair, K=512): h = gelu(t @ w2)
    mma_gemm<2><<<dim3(FFN / 256, MAXT2), NTHREADS, SMEM_BYTES>>>(nullptr, nullptr);
    // Stage 3 (dense): out = h @ lin2 + b
    mma_gemm<3><<<dim3(HID / 256, TOK / 128), NTHREADS, SMEM_BYTES>>>(lin2_b, out);
}